// round 3
// baseline (speedup 1.0000x reference)
#include <cuda_runtime.h>
#include <cuda_fp16.h>
#include <cstdint>

#define BSZ   256
#define MM    128
#define NN    1024
#define ITERS 100
#define ALPHA 0.1f

// Scratch
__device__ __half g_Ah[(size_t)BSZ * MM * NN];   // A fp16, 67 MB
__device__ float  g_C [(size_t)BSZ * MM * MM];   // AAT partial 0 -> inverse
__device__ float  g_C2[(size_t)BSZ * MM * MM];   // AAT partial 1

// ---------------------------------------------------------------------------
// helpers
// ---------------------------------------------------------------------------
__device__ __forceinline__ uint32_t smem_u32(const void* p) {
    uint32_t a;
    asm("{ .reg .u64 t; cvta.to.shared.u64 t, %1; cvt.u32.u64 %0, t; }"
        : "=r"(a) : "l"(p));
    return a;
}
__device__ __forceinline__ uint32_t mapa_rank(uint32_t addr, uint32_t trank) {
    uint32_t r;
    asm("mapa.shared::cluster.u32 %0, %1, %2;" : "=r"(r) : "r"(addr), "r"(trank));
    return r;
}
__device__ __forceinline__ void cluster_sync_() {
    asm volatile("barrier.cluster.arrive.aligned;" ::: "memory");
    asm volatile("barrier.cluster.wait.aligned;"   ::: "memory");
}
__device__ __forceinline__ void st_cluster_f32(uint32_t addr, float v) {
    asm volatile("st.shared::cluster.f32 [%0], %1;" :: "r"(addr), "f"(v) : "memory");
}

// ---------------------------------------------------------------------------
// Kernel 1: convert A fp32 -> fp16
// ---------------------------------------------------------------------------
__global__ void k_convert(const float* __restrict__ A) {
    size_t i = ((size_t)blockIdx.x * blockDim.x + threadIdx.x) * 4;
    float4 v = *(const float4*)(A + i);
    __half2* dst = (__half2*)(g_Ah + i);
    dst[0] = __floats2half2_rn(v.x, v.y);
    dst[1] = __floats2half2_rn(v.z, v.w);
}

// ---------------------------------------------------------------------------
// Kernel 2: AAT partials, symmetric-triangle + K-split(2).
// grid = BSZ*2; CTA (b, kc) accumulates A[:,kc*512 .. +512) outer products.
// Thread (ty,tx) owns elements (ty+16ii, tx+16jj): computes ii>jj fully,
// ii==jj only when ty>=tx, mirrors on write.
// ---------------------------------------------------------------------------
__global__ void __launch_bounds__(256) k_aat() {
    __shared__ float sA[128 * 33];
    int b = blockIdx.x >> 1, kc = blockIdx.x & 1, t = threadIdx.x;
    const __half* Ab = g_Ah + (size_t)b * MM * NN;
    int ty = t >> 4, tx = t & 15;
    bool dg = (ty >= tx);

    float acc[8][8];
#pragma unroll
    for (int ii = 0; ii < 8; ii++)
#pragma unroll
        for (int jj = 0; jj < 8; jj++) acc[ii][jj] = 0.0f;

    for (int ks = 0; ks < 16; ks++) {
        int k0 = kc * 512 + ks * 32;
        int tr = t >> 1, tc0 = (t & 1) * 16;
        const __half2* src = (const __half2*)(Ab + (size_t)tr * NN + k0 + tc0);
        float* dst = &sA[tr * 33 + tc0];
#pragma unroll
        for (int q = 0; q < 8; q++) {
            float2 f = __half22float2(src[q]);
            dst[2 * q] = f.x; dst[2 * q + 1] = f.y;
        }
        __syncthreads();

#pragma unroll 2
        for (int kk = 0; kk < 32; kk++) {
            float a[8], c[8];
#pragma unroll
            for (int ii = 0; ii < 8; ii++) a[ii] = sA[(ty + 16 * ii) * 33 + kk];
#pragma unroll
            for (int jj = 0; jj < 8; jj++) c[jj] = sA[(tx + 16 * jj) * 33 + kk];
#pragma unroll
            for (int ii = 1; ii < 8; ii++)
#pragma unroll
                for (int jj = 0; jj < ii; jj++)
                    acc[ii][jj] += a[ii] * c[jj];
            if (dg) {
#pragma unroll
                for (int ii = 0; ii < 8; ii++)
                    acc[ii][ii] += a[ii] * c[ii];
            }
        }
        __syncthreads();
    }

    float* Cb = (kc ? g_C2 : g_C) + (size_t)b * MM * MM;
#pragma unroll
    for (int ii = 1; ii < 8; ii++)
#pragma unroll
        for (int jj = 0; jj < ii; jj++) {
            int r = ty + 16 * ii, c = tx + 16 * jj;
            Cb[r * MM + c] = acc[ii][jj];
            Cb[c * MM + r] = acc[ii][jj];
        }
    if (dg) {
#pragma unroll
        for (int ii = 0; ii < 8; ii++) {
            int r = ty + 16 * ii, c = tx + 16 * ii;
            Cb[r * MM + c] = acc[ii][ii];
            Cb[c * MM + r] = acc[ii][ii];
        }
    }
}

// ---------------------------------------------------------------------------
// Kernel 3: Gauss-Jordan inverse of (C1+C2), result into g_C.
// ---------------------------------------------------------------------------
__global__ void __launch_bounds__(256) k_inv() {
    extern __shared__ float sm[];
    float* sM = sm;
    float* sf = sm + 16384;
    float* sp = sm + 16512;
    int b = blockIdx.x, t = threadIdx.x;
    float* Cb  = g_C  + (size_t)b * MM * MM;
    const float* Cb2 = g_C2 + (size_t)b * MM * MM;

    for (int i = t; i < 4096; i += 256) {
        float4 x = ((const float4*)Cb)[i], y = ((const float4*)Cb2)[i];
        ((float4*)sM)[i] = make_float4(x.x + y.x, x.y + y.y, x.z + y.z, x.w + y.w);
    }
    __syncthreads();

    for (int k = 0; k < 128; k++) {
        if (t == 0) sp[0] = 1.0f / sM[k * 128 + k];
        __syncthreads();
        float ipiv = sp[0];
        if (t < 128) {
            float v = sM[k * 128 + t];
            sM[k * 128 + t] = (t == k) ? ipiv : v * ipiv;
            sf[t] = (t == k) ? 0.0f : sM[t * 128 + k];
        }
        __syncthreads();
        int j = t & 127, i0 = (t >> 7) * 64;
        float mk = sM[k * 128 + j];
#pragma unroll 4
        for (int ii = 0; ii < 64; ii++) {
            int i = i0 + ii;
            if (i == k) continue;
            float fi = sf[i];
            float v = sM[i * 128 + j];
            sM[i * 128 + j] = (j == k) ? (-fi * mk) : (v - fi * mk);
        }
        __syncthreads();
    }
    for (int i = t; i < 4096; i += 256) ((float4*)Cb)[i] = ((const float4*)sM)[i];
}

// ---------------------------------------------------------------------------
// Kernel 4: iterations. 2-CTA cluster per batch, A half + C resident in smem.
// ---------------------------------------------------------------------------
#define OFF_C   0          // 16384 f  : AAT^{-1}
#define OFF_A   16384      // 32768 w  : A half as half2-words (128 x 256)
#define OFF_Y   49152      // 512  f   : y local half
#define OFF_B   49664      // 128  f   : b
#define OFF_R   49792      // 128  f   : local partial r
#define OFF_REM 49920      // 256  f   : peer partial r (double buffer)
#define OFF_RT  50176      // 128  f   : r total
#define OFF_U   50304      // 128  f   : u
#define OFF_CMB 50432      // 512  f   : pass2 combine
#define SMEM_WORDS 50944   // 203776 bytes

__global__ void __launch_bounds__(512, 1) __cluster_dims__(2, 1, 1)
k_iter(const float* __restrict__ bvec,
       const float* __restrict__ D1,
       const float* __restrict__ D2,
       float* __restrict__ out) {
    extern __shared__ float sm[];
    const int t = threadIdx.x, w = t >> 5, l = t & 31;
    const int b = blockIdx.x >> 1;
    const uint32_t rank = blockIdx.x & 1;
    const uint32_t sbase = smem_u32(sm);

    // ---- load phase ----
    {   // C: 4096 float4
        float4* d = (float4*)(sm + OFF_C);
        const float4* s = (const float4*)(g_C + (size_t)b * MM * MM);
#pragma unroll
        for (int q = 0; q < 8; q++) d[t + 512 * q] = s[t + 512 * q];
        // A half: 8192 uint4 (rows 0..127, local cols 0..511)
        uint4* da = (uint4*)(sm + OFF_A);
        const uint4* sa = (const uint4*)(g_Ah + (size_t)b * MM * NN + (size_t)rank * 512);
#pragma unroll
        for (int q = 0; q < 16; q++) {
            int i = t + 512 * q;          // i = r*64 + c4
            int r = i >> 6, c4 = i & 63;
            da[i] = sa[(size_t)r * 128 + c4];
        }
        if (t < 128) sm[OFF_B + t] = bvec[(size_t)b * MM + t];
    }

    // per-thread state: thread t<256 owns local cols 2t, 2t+1
    float2 thr2 = make_float2(0.f, 0.f), dv2 = make_float2(0.f, 0.f);
    float2 z2 = make_float2(0.f, 0.f), xh2, yv2 = make_float2(0.f, 0.f);
    float cx = 0.f, cy = 0.f;
    if (t < 256) {
        float2 d1 = ((const float2*)(D1 + (size_t)b * NN + rank * 512))[t];
        float2 d2 = ((const float2*)(D2 + (size_t)b * NN + rank * 512))[t];
        thr2.x = ALPHA * fabsf(d1.x); thr2.y = ALPHA * fabsf(d1.y);
        dv2.x = 1.0f / (1.0f + 2.0f * ALPHA * d2.x * d2.x);
        dv2.y = 1.0f / (1.0f + 2.0f * ALPHA * d2.y * d2.y);
    }
    __syncthreads();

    for (int it = 0; it < ITERS; it++) {
        // --- elementwise: x_half = soft(z), y = 2*x_half - z ---
        if (t < 256) {
            float a0 = z2.x - thr2.x, c0 = z2.x + thr2.x;
            float a1 = z2.y - thr2.y, c1 = z2.y + thr2.y;
            xh2.x = (a0 > 0.f) ? a0 * dv2.x : ((c0 < 0.f) ? c0 * dv2.x : 0.f);
            xh2.y = (a1 > 0.f) ? a1 * dv2.y : ((c1 < 0.f) ? c1 * dv2.y : 0.f);
            yv2.x = 2.0f * xh2.x - z2.x;
            yv2.y = 2.0f * xh2.y - z2.y;
            ((float2*)(sm + OFF_Y))[t] = yv2;
        }
        __syncthreads();

        // --- pass 1: partial r = A_half * y_half. warp w -> rows 8w..8w+7 ---
        {
            float4 yr[4];
            const float4* y4 = (const float4*)(sm + OFF_Y);
#pragma unroll
            for (int q = 0; q < 4; q++) yr[q] = y4[4 * l + q];

            const uint4* a4 = (const uint4*)(sm + OFF_A);
#pragma unroll 2
            for (int rr = 0; rr < 8; rr++) {
                int r = 8 * w + rr;
                uint4 p0 = a4[r * 64 + 2 * l];
                uint4 p1 = a4[r * 64 + 2 * l + 1];
                float acc;
                float2 f;
                f = __half22float2(*(__half2*)&p0.x); acc  = f.x * yr[0].x + f.y * yr[0].y;
                f = __half22float2(*(__half2*)&p0.y); acc += f.x * yr[0].z + f.y * yr[0].w;
                f = __half22float2(*(__half2*)&p0.z); acc += f.x * yr[1].x + f.y * yr[1].y;
                f = __half22float2(*(__half2*)&p0.w); acc += f.x * yr[1].z + f.y * yr[1].w;
                f = __half22float2(*(__half2*)&p1.x); acc += f.x * yr[2].x + f.y * yr[2].y;
                f = __half22float2(*(__half2*)&p1.y); acc += f.x * yr[2].z + f.y * yr[2].w;
                f = __half22float2(*(__half2*)&p1.z); acc += f.x * yr[3].x + f.y * yr[3].y;
                f = __half22float2(*(__half2*)&p1.w); acc += f.x * yr[3].z + f.y * yr[3].w;
#pragma unroll
                for (int off = 16; off > 0; off >>= 1)
                    acc += __shfl_xor_sync(0xffffffffu, acc, off);
                if (l == 0) sm[OFF_R + r] = acc;
            }
        }
        __syncthreads();

        // --- push my partial into peer's srem[it&1] ---
        if (w == 0) {
            float4 mine = *(const float4*)(sm + OFF_R + 4 * l);
            uint32_t laddr = sbase + (uint32_t)(OFF_REM + (it & 1) * 128 + 4 * l) * 4u;
            uint32_t raddr = mapa_rank(laddr, rank ^ 1u);
            st_cluster_f32(raddr,      mine.x);
            st_cluster_f32(raddr + 4,  mine.y);
            st_cluster_f32(raddr + 8,  mine.z);
            st_cluster_f32(raddr + 12, mine.w);
        }
        cluster_sync_();

        // --- r_total = mine + peer - b ---
        if (t < 128)
            sm[OFF_RT + t] = sm[OFF_R + t] + sm[OFF_REM + (it & 1) * 128 + t] - sm[OFF_B + t];
        __syncthreads();

        // --- u = C * r_total (threads 0..255, 2 per row, staggered) ---
        if (t < 256) {
            int i = t >> 1, h = t & 1, base = i & 15;
            float accu = 0.0f;
#pragma unroll
            for (int m = 0; m < 16; m++) {
                int j = 64 * h + 4 * ((base + m) & 15);
                float4 c4 = *(const float4*)(sm + OFF_C + i * 128 + j);
                float4 r4 = *(const float4*)(sm + OFF_RT + j);
                accu += c4.x * r4.x + c4.y * r4.y + c4.z * r4.z + c4.w * r4.w;
            }
            accu += __shfl_xor_sync(0xffffffffu, accu, 1);
            if (h == 0) sm[OFF_U + i] = accu;
        }
        __syncthreads();

        // --- pass 2: corr[2p..2p+1] = sum_r A[r][2p..2p+1]*u[r], rows split g ---
        {
            int g = t >> 8, p = t & 255;
            cx = 0.f; cy = 0.f;
            const unsigned* acol = (const unsigned*)(sm + OFF_A) + p;
            const float4* u4p = (const float4*)(sm + OFF_U) + g * 16;
#pragma unroll 4
            for (int m = 0; m < 16; m++) {
                float4 u4 = u4p[m];
                int r0 = 64 * g + 4 * m;
                float2 f;
                f = __half22float2(*(const __half2*)&acol[(r0 + 0) * 256]); cx += f.x * u4.x; cy += f.y * u4.x;
                f = __half22float2(*(const __half2*)&acol[(r0 + 1) * 256]); cx += f.x * u4.y; cy += f.y * u4.y;
                f = __half22float2(*(const __half2*)&acol[(r0 + 2) * 256]); cx += f.x * u4.z; cy += f.y * u4.z;
                f = __half22float2(*(const __half2*)&acol[(r0 + 3) * 256]); cx += f.x * u4.w; cy += f.y * u4.w;
            }
            if (g == 1) ((float2*)(sm + OFF_CMB))[p] = make_float2(cx, cy);
        }
        __syncthreads();

        // --- epilogue on owners (t<256): x_new = y - corr, z' = x_half - corr ---
        if (t < 256) {
            float2 o = ((const float2*)(sm + OFF_CMB))[t];
            cx += o.x; cy += o.y;
            z2.x = xh2.x - cx; z2.y = xh2.y - cy;
            yv2.x -= cx; yv2.y -= cy;           // = x_new, kept for output
        }
    }

    if (t < 256)
        ((float2*)(out + (size_t)b * NN + rank * 512))[t] = yv2;
}

// ---------------------------------------------------------------------------
extern "C" void kernel_launch(void* const* d_in, const int* in_sizes, int n_in,
                              void* d_out, int out_size) {
    const float* A  = (const float*)d_in[0];
    const float* bv = (const float*)d_in[1];
    const float* D1 = (const float*)d_in[2];
    const float* D2 = (const float*)d_in[3];
    float* out = (float*)d_out;

    cudaFuncSetAttribute(k_inv,  cudaFuncAttributeMaxDynamicSharedMemorySize, 66052);
    cudaFuncSetAttribute(k_iter, cudaFuncAttributeMaxDynamicSharedMemorySize, SMEM_WORDS * 4);

    k_convert<<<32768, 256>>>(A);
    k_aat<<<BSZ * 2, 256>>>();
    k_inv<<<BSZ, 256, 66052>>>();
    k_iter<<<BSZ * 2, 512, SMEM_WORDS * 4>>>(bv, D1, D2, out);
}

// round 4
// speedup vs baseline: 1.0016x; 1.0016x over previous
#include <cuda_runtime.h>
#include <cuda_fp16.h>
#include <cstdint>

#define BSZ   256
#define MM    128
#define NN    1024
#define ITERS 100
#define ALPHA 0.1f

// Scratch
__device__ __half g_Ah[(size_t)BSZ * MM * NN];   // A fp16, 67 MB
__device__ float  g_C [(size_t)BSZ * MM * MM];   // AAT partial 0 -> inverse
__device__ float  g_C2[(size_t)BSZ * MM * MM];   // AAT partial 1

// ---------------------------------------------------------------------------
// helpers
// ---------------------------------------------------------------------------
__device__ __forceinline__ uint32_t smem_u32(const void* p) {
    uint32_t a;
    asm("{ .reg .u64 t; cvta.to.shared.u64 t, %1; cvt.u32.u64 %0, t; }"
        : "=r"(a) : "l"(p));
    return a;
}
__device__ __forceinline__ uint32_t mapa_rank(uint32_t addr, uint32_t trank) {
    uint32_t r;
    asm("mapa.shared::cluster.u32 %0, %1, %2;" : "=r"(r) : "r"(addr), "r"(trank));
    return r;
}
__device__ __forceinline__ void cluster_sync_() {
    asm volatile("barrier.cluster.arrive.aligned;" ::: "memory");
    asm volatile("barrier.cluster.wait.aligned;"   ::: "memory");
}
__device__ __forceinline__ void st_cluster_f32(uint32_t addr, float v) {
    asm volatile("st.shared::cluster.f32 [%0], %1;" :: "r"(addr), "f"(v) : "memory");
}

// ---------------------------------------------------------------------------
// Kernel 1: convert A fp32 -> fp16
// ---------------------------------------------------------------------------
__global__ void k_convert(const float* __restrict__ A) {
    size_t i = ((size_t)blockIdx.x * blockDim.x + threadIdx.x) * 4;
    float4 v = *(const float4*)(A + i);
    __half2* dst = (__half2*)(g_Ah + i);
    dst[0] = __floats2half2_rn(v.x, v.y);
    dst[1] = __floats2half2_rn(v.z, v.w);
}

// ---------------------------------------------------------------------------
// Kernel 2: AAT partials, symmetric-triangle + K-split(2).
// grid = BSZ*2; CTA (b, kc) accumulates A[:,kc*512 .. +512) outer products.
// Thread (ty,tx) owns elements (ty+16ii, tx+16jj): computes ii>jj fully,
// ii==jj only when ty>=tx, mirrors on write.
// ---------------------------------------------------------------------------
__global__ void __launch_bounds__(256) k_aat() {
    __shared__ float sA[128 * 33];
    int b = blockIdx.x >> 1, kc = blockIdx.x & 1, t = threadIdx.x;
    const __half* Ab = g_Ah + (size_t)b * MM * NN;
    int ty = t >> 4, tx = t & 15;
    bool dg = (ty >= tx);

    float acc[8][8];
#pragma unroll
    for (int ii = 0; ii < 8; ii++)
#pragma unroll
        for (int jj = 0; jj < 8; jj++) acc[ii][jj] = 0.0f;

    for (int ks = 0; ks < 16; ks++) {
        int k0 = kc * 512 + ks * 32;
        int tr = t >> 1, tc0 = (t & 1) * 16;
        const __half2* src = (const __half2*)(Ab + (size_t)tr * NN + k0 + tc0);
        float* dst = &sA[tr * 33 + tc0];
#pragma unroll
        for (int q = 0; q < 8; q++) {
            float2 f = __half22float2(src[q]);
            dst[2 * q] = f.x; dst[2 * q + 1] = f.y;
        }
        __syncthreads();

#pragma unroll 2
        for (int kk = 0; kk < 32; kk++) {
            float a[8], c[8];
#pragma unroll
            for (int ii = 0; ii < 8; ii++) a[ii] = sA[(ty + 16 * ii) * 33 + kk];
#pragma unroll
            for (int jj = 0; jj < 8; jj++) c[jj] = sA[(tx + 16 * jj) * 33 + kk];
#pragma unroll
            for (int ii = 1; ii < 8; ii++)
#pragma unroll
                for (int jj = 0; jj < ii; jj++)
                    acc[ii][jj] += a[ii] * c[jj];
            if (dg) {
#pragma unroll
                for (int ii = 0; ii < 8; ii++)
                    acc[ii][ii] += a[ii] * c[ii];
            }
        }
        __syncthreads();
    }

    float* Cb = (kc ? g_C2 : g_C) + (size_t)b * MM * MM;
#pragma unroll
    for (int ii = 1; ii < 8; ii++)
#pragma unroll
        for (int jj = 0; jj < ii; jj++) {
            int r = ty + 16 * ii, c = tx + 16 * jj;
            Cb[r * MM + c] = acc[ii][jj];
            Cb[c * MM + r] = acc[ii][jj];
        }
    if (dg) {
#pragma unroll
        for (int ii = 0; ii < 8; ii++) {
            int r = ty + 16 * ii, c = tx + 16 * ii;
            Cb[r * MM + c] = acc[ii][ii];
            Cb[c * MM + r] = acc[ii][ii];
        }
    }
}

// ---------------------------------------------------------------------------
// Kernel 3: Gauss-Jordan inverse of (C1+C2), result into g_C.
// ---------------------------------------------------------------------------
__global__ void __launch_bounds__(256) k_inv() {
    extern __shared__ float sm[];
    float* sM = sm;
    float* sf = sm + 16384;
    float* sp = sm + 16512;
    int b = blockIdx.x, t = threadIdx.x;
    float* Cb  = g_C  + (size_t)b * MM * MM;
    const float* Cb2 = g_C2 + (size_t)b * MM * MM;

    for (int i = t; i < 4096; i += 256) {
        float4 x = ((const float4*)Cb)[i], y = ((const float4*)Cb2)[i];
        ((float4*)sM)[i] = make_float4(x.x + y.x, x.y + y.y, x.z + y.z, x.w + y.w);
    }
    __syncthreads();

    for (int k = 0; k < 128; k++) {
        if (t == 0) sp[0] = 1.0f / sM[k * 128 + k];
        __syncthreads();
        float ipiv = sp[0];
        if (t < 128) {
            float v = sM[k * 128 + t];
            sM[k * 128 + t] = (t == k) ? ipiv : v * ipiv;
            sf[t] = (t == k) ? 0.0f : sM[t * 128 + k];
        }
        __syncthreads();
        int j = t & 127, i0 = (t >> 7) * 64;
        float mk = sM[k * 128 + j];
#pragma unroll 4
        for (int ii = 0; ii < 64; ii++) {
            int i = i0 + ii;
            if (i == k) continue;
            float fi = sf[i];
            float v = sM[i * 128 + j];
            sM[i * 128 + j] = (j == k) ? (-fi * mk) : (v - fi * mk);
        }
        __syncthreads();
    }
    for (int i = t; i < 4096; i += 256) ((float4*)Cb)[i] = ((const float4*)sM)[i];
}

// ---------------------------------------------------------------------------
// Kernel 4: iterations. 2-CTA cluster per batch, A half + C resident in smem.
// ---------------------------------------------------------------------------
#define OFF_C   0          // 16384 f  : AAT^{-1}
#define OFF_A   16384      // 32768 w  : A half as half2-words (128 x 256)
#define OFF_Y   49152      // 512  f   : y local half
#define OFF_B   49664      // 128  f   : b
#define OFF_R   49792      // 128  f   : local partial r
#define OFF_REM 49920      // 256  f   : peer partial r (double buffer)
#define OFF_RT  50176      // 128  f   : r total
#define OFF_U   50304      // 128  f   : u
#define OFF_CMB 50432      // 512  f   : pass2 combine
#define SMEM_WORDS 50944   // 203776 bytes

__global__ void __launch_bounds__(512, 1) __cluster_dims__(2, 1, 1)
k_iter(const float* __restrict__ bvec,
       const float* __restrict__ D1,
       const float* __restrict__ D2,
       float* __restrict__ out) {
    extern __shared__ float sm[];
    const int t = threadIdx.x, w = t >> 5, l = t & 31;
    const int b = blockIdx.x >> 1;
    const uint32_t rank = blockIdx.x & 1;
    const uint32_t sbase = smem_u32(sm);

    // ---- load phase ----
    {   // C: 4096 float4
        float4* d = (float4*)(sm + OFF_C);
        const float4* s = (const float4*)(g_C + (size_t)b * MM * MM);
#pragma unroll
        for (int q = 0; q < 8; q++) d[t + 512 * q] = s[t + 512 * q];
        // A half: 8192 uint4 (rows 0..127, local cols 0..511)
        uint4* da = (uint4*)(sm + OFF_A);
        const uint4* sa = (const uint4*)(g_Ah + (size_t)b * MM * NN + (size_t)rank * 512);
#pragma unroll
        for (int q = 0; q < 16; q++) {
            int i = t + 512 * q;          // i = r*64 + c4
            int r = i >> 6, c4 = i & 63;
            da[i] = sa[(size_t)r * 128 + c4];
        }
        if (t < 128) sm[OFF_B + t] = bvec[(size_t)b * MM + t];
    }

    // per-thread state: thread t<256 owns local cols 2t, 2t+1
    float2 thr2 = make_float2(0.f, 0.f), dv2 = make_float2(0.f, 0.f);
    float2 z2 = make_float2(0.f, 0.f), xh2, yv2 = make_float2(0.f, 0.f);
    float cx = 0.f, cy = 0.f;
    if (t < 256) {
        float2 d1 = ((const float2*)(D1 + (size_t)b * NN + rank * 512))[t];
        float2 d2 = ((const float2*)(D2 + (size_t)b * NN + rank * 512))[t];
        thr2.x = ALPHA * fabsf(d1.x); thr2.y = ALPHA * fabsf(d1.y);
        dv2.x = 1.0f / (1.0f + 2.0f * ALPHA * d2.x * d2.x);
        dv2.y = 1.0f / (1.0f + 2.0f * ALPHA * d2.y * d2.y);
    }
    __syncthreads();

    for (int it = 0; it < ITERS; it++) {
        // --- elementwise: x_half = soft(z), y = 2*x_half - z ---
        if (t < 256) {
            float a0 = z2.x - thr2.x, c0 = z2.x + thr2.x;
            float a1 = z2.y - thr2.y, c1 = z2.y + thr2.y;
            xh2.x = (a0 > 0.f) ? a0 * dv2.x : ((c0 < 0.f) ? c0 * dv2.x : 0.f);
            xh2.y = (a1 > 0.f) ? a1 * dv2.y : ((c1 < 0.f) ? c1 * dv2.y : 0.f);
            yv2.x = 2.0f * xh2.x - z2.x;
            yv2.y = 2.0f * xh2.y - z2.y;
            ((float2*)(sm + OFF_Y))[t] = yv2;
        }
        __syncthreads();

        // --- pass 1: partial r = A_half * y_half. warp w -> rows 8w..8w+7 ---
        {
            float4 yr[4];
            const float4* y4 = (const float4*)(sm + OFF_Y);
#pragma unroll
            for (int q = 0; q < 4; q++) yr[q] = y4[4 * l + q];

            const uint4* a4 = (const uint4*)(sm + OFF_A);
#pragma unroll 2
            for (int rr = 0; rr < 8; rr++) {
                int r = 8 * w + rr;
                uint4 p0 = a4[r * 64 + 2 * l];
                uint4 p1 = a4[r * 64 + 2 * l + 1];
                float acc;
                float2 f;
                f = __half22float2(*(__half2*)&p0.x); acc  = f.x * yr[0].x + f.y * yr[0].y;
                f = __half22float2(*(__half2*)&p0.y); acc += f.x * yr[0].z + f.y * yr[0].w;
                f = __half22float2(*(__half2*)&p0.z); acc += f.x * yr[1].x + f.y * yr[1].y;
                f = __half22float2(*(__half2*)&p0.w); acc += f.x * yr[1].z + f.y * yr[1].w;
                f = __half22float2(*(__half2*)&p1.x); acc += f.x * yr[2].x + f.y * yr[2].y;
                f = __half22float2(*(__half2*)&p1.y); acc += f.x * yr[2].z + f.y * yr[2].w;
                f = __half22float2(*(__half2*)&p1.z); acc += f.x * yr[3].x + f.y * yr[3].y;
                f = __half22float2(*(__half2*)&p1.w); acc += f.x * yr[3].z + f.y * yr[3].w;
#pragma unroll
                for (int off = 16; off > 0; off >>= 1)
                    acc += __shfl_xor_sync(0xffffffffu, acc, off);
                if (l == 0) sm[OFF_R + r] = acc;
            }
        }
        __syncthreads();

        // --- push my partial into peer's srem[it&1] ---
        if (w == 0) {
            float4 mine = *(const float4*)(sm + OFF_R + 4 * l);
            uint32_t laddr = sbase + (uint32_t)(OFF_REM + (it & 1) * 128 + 4 * l) * 4u;
            uint32_t raddr = mapa_rank(laddr, rank ^ 1u);
            st_cluster_f32(raddr,      mine.x);
            st_cluster_f32(raddr + 4,  mine.y);
            st_cluster_f32(raddr + 8,  mine.z);
            st_cluster_f32(raddr + 12, mine.w);
        }
        cluster_sync_();

        // --- r_total = mine + peer - b ---
        if (t < 128)
            sm[OFF_RT + t] = sm[OFF_R + t] + sm[OFF_REM + (it & 1) * 128 + t] - sm[OFF_B + t];
        __syncthreads();

        // --- u = C * r_total (threads 0..255, 2 per row, staggered) ---
        if (t < 256) {
            int i = t >> 1, h = t & 1, base = i & 15;
            float accu = 0.0f;
#pragma unroll
            for (int m = 0; m < 16; m++) {
                int j = 64 * h + 4 * ((base + m) & 15);
                float4 c4 = *(const float4*)(sm + OFF_C + i * 128 + j);
                float4 r4 = *(const float4*)(sm + OFF_RT + j);
                accu += c4.x * r4.x + c4.y * r4.y + c4.z * r4.z + c4.w * r4.w;
            }
            accu += __shfl_xor_sync(0xffffffffu, accu, 1);
            if (h == 0) sm[OFF_U + i] = accu;
        }
        __syncthreads();

        // --- pass 2: corr[2p..2p+1] = sum_r A[r][2p..2p+1]*u[r], rows split g ---
        {
            int g = t >> 8, p = t & 255;
            cx = 0.f; cy = 0.f;
            const unsigned* acol = (const unsigned*)(sm + OFF_A) + p;
            const float4* u4p = (const float4*)(sm + OFF_U) + g * 16;
#pragma unroll 4
            for (int m = 0; m < 16; m++) {
                float4 u4 = u4p[m];
                int r0 = 64 * g + 4 * m;
                float2 f;
                f = __half22float2(*(const __half2*)&acol[(r0 + 0) * 256]); cx += f.x * u4.x; cy += f.y * u4.x;
                f = __half22float2(*(const __half2*)&acol[(r0 + 1) * 256]); cx += f.x * u4.y; cy += f.y * u4.y;
                f = __half22float2(*(const __half2*)&acol[(r0 + 2) * 256]); cx += f.x * u4.z; cy += f.y * u4.z;
                f = __half22float2(*(const __half2*)&acol[(r0 + 3) * 256]); cx += f.x * u4.w; cy += f.y * u4.w;
            }
            if (g == 1) ((float2*)(sm + OFF_CMB))[p] = make_float2(cx, cy);
        }
        __syncthreads();

        // --- epilogue on owners (t<256): x_new = y - corr, z' = x_half - corr ---
        if (t < 256) {
            float2 o = ((const float2*)(sm + OFF_CMB))[t];
            cx += o.x; cy += o.y;
            z2.x = xh2.x - cx; z2.y = xh2.y - cy;
            yv2.x -= cx; yv2.y -= cy;           // = x_new, kept for output
        }
    }

    if (t < 256)
        ((float2*)(out + (size_t)b * NN + rank * 512))[t] = yv2;
}

// ---------------------------------------------------------------------------
extern "C" void kernel_launch(void* const* d_in, const int* in_sizes, int n_in,
                              void* d_out, int out_size) {
    const float* A  = (const float*)d_in[0];
    const float* bv = (const float*)d_in[1];
    const float* D1 = (const float*)d_in[2];
    const float* D2 = (const float*)d_in[3];
    float* out = (float*)d_out;

    cudaFuncSetAttribute(k_inv,  cudaFuncAttributeMaxDynamicSharedMemorySize, 66052);
    cudaFuncSetAttribute(k_iter, cudaFuncAttributeMaxDynamicSharedMemorySize, SMEM_WORDS * 4);

    k_convert<<<32768, 256>>>(A);
    k_aat<<<BSZ * 2, 256>>>();
    k_inv<<<BSZ, 256, 66052>>>();
    k_iter<<<BSZ * 2, 512, SMEM_WORDS * 4>>>(bv, D1, D2, out);
}

// round 5
// speedup vs baseline: 1.2728x; 1.2707x over previous
#include <cuda_runtime.h>
#include <cuda_fp16.h>
#include <cstdint>

#define BSZ   256
#define MM    128
#define NN    1024
#define ITERS 100
#define ALPHA 0.1f

__device__ __half g_Ah[(size_t)BSZ * MM * NN];
__device__ float  g_C [(size_t)BSZ * MM * MM];
__device__ float  g_C2[(size_t)BSZ * MM * MM];

typedef unsigned long long u64;

__device__ __forceinline__ uint32_t smem_u32(const void* p) {
    uint32_t a;
    asm("{ .reg .u64 t; cvta.to.shared.u64 t, %1; cvt.u32.u64 %0, t; }" : "=r"(a) : "l"(p));
    return a;
}
__device__ __forceinline__ uint32_t mapa_rank(uint32_t addr, uint32_t trank) {
    uint32_t r;
    asm("mapa.shared::cluster.u32 %0, %1, %2;" : "=r"(r) : "r"(addr), "r"(trank));
    return r;
}
__device__ __forceinline__ void cluster_sync_() {
    asm volatile("barrier.cluster.arrive.aligned;" ::: "memory");
    asm volatile("barrier.cluster.wait.aligned;"   ::: "memory");
}
__device__ __forceinline__ void st_cluster_f32(uint32_t addr, float v) {
    asm volatile("st.shared::cluster.f32 [%0], %1;" :: "r"(addr), "f"(v) : "memory");
}
__device__ __forceinline__ void mbar_init(uint32_t a, uint32_t c) {
    asm volatile("mbarrier.init.shared.b64 [%0], %1;" :: "r"(a), "r"(c) : "memory");
}
__device__ __forceinline__ void mbar_arrive_remote(uint32_t ra) {
    asm volatile("mbarrier.arrive.release.cluster.shared::cluster.b64 _, [%0];" :: "r"(ra) : "memory");
}
__device__ __forceinline__ void mbar_wait_acq(uint32_t mb, uint32_t par) {
    asm volatile(
        "{\n\t.reg .pred P;\n\t"
        "WL%=:\n\t"
        "mbarrier.try_wait.parity.acquire.cluster.shared::cta.b64 P, [%0], %1, 0x989680;\n\t"
        "@P bra.uni WD%=;\n\t"
        "bra.uni WL%=;\n\t"
        "WD%=:\n\t}" :: "r"(mb), "r"(par) : "memory");
}
// packed f32x2 helpers
__device__ __forceinline__ u64 pk(float2 f) {
    u64 r; asm("mov.b64 %0, {%1, %2};" : "=l"(r) : "f"(f.x), "f"(f.y)); return r;
}
__device__ __forceinline__ void fma2(u64& acc, u64 a, u64 b) {
    asm("fma.rn.f32x2 %0, %1, %2, %0;" : "+l"(acc) : "l"(a), "l"(b));
}
__device__ __forceinline__ float2 upk(u64 v) {
    float2 f; asm("mov.b64 {%0, %1}, %2;" : "=f"(f.x), "=f"(f.y) : "l"(v)); return f;
}

// --------------------------------------------------------------------------
__global__ void k_convert(const float* __restrict__ A) {
    size_t i = ((size_t)blockIdx.x * blockDim.x + threadIdx.x) * 4;
    float4 v = *(const float4*)(A + i);
    __half2* dst = (__half2*)(g_Ah + i);
    dst[0] = __floats2half2_rn(v.x, v.y);
    dst[1] = __floats2half2_rn(v.z, v.w);
}

// AAT partials (triangle + K-split 2) -------------------------------------
__global__ void __launch_bounds__(256) k_aat() {
    __shared__ float sA[128 * 33];
    int b = blockIdx.x >> 1, kc = blockIdx.x & 1, t = threadIdx.x;
    const __half* Ab = g_Ah + (size_t)b * MM * NN;
    int ty = t >> 4, tx = t & 15;
    bool dg = (ty >= tx);
    float acc[8][8];
#pragma unroll
    for (int ii = 0; ii < 8; ii++)
#pragma unroll
        for (int jj = 0; jj < 8; jj++) acc[ii][jj] = 0.0f;

    for (int ks = 0; ks < 16; ks++) {
        int k0 = kc * 512 + ks * 32;
        int tr = t >> 1, tc0 = (t & 1) * 16;
        const __half2* src = (const __half2*)(Ab + (size_t)tr * NN + k0 + tc0);
        float* dst = &sA[tr * 33 + tc0];
#pragma unroll
        for (int q = 0; q < 8; q++) {
            float2 f = __half22float2(src[q]);
            dst[2 * q] = f.x; dst[2 * q + 1] = f.y;
        }
        __syncthreads();
#pragma unroll 2
        for (int kk = 0; kk < 32; kk++) {
            float a[8], c[8];
#pragma unroll
            for (int ii = 0; ii < 8; ii++) a[ii] = sA[(ty + 16 * ii) * 33 + kk];
#pragma unroll
            for (int jj = 0; jj < 8; jj++) c[jj] = sA[(tx + 16 * jj) * 33 + kk];
#pragma unroll
            for (int ii = 1; ii < 8; ii++)
#pragma unroll
                for (int jj = 0; jj < ii; jj++) acc[ii][jj] += a[ii] * c[jj];
            if (dg) {
#pragma unroll
                for (int ii = 0; ii < 8; ii++) acc[ii][ii] += a[ii] * c[ii];
            }
        }
        __syncthreads();
    }
    float* Cb = (kc ? g_C2 : g_C) + (size_t)b * MM * MM;
#pragma unroll
    for (int ii = 1; ii < 8; ii++)
#pragma unroll
        for (int jj = 0; jj < ii; jj++) {
            int r = ty + 16 * ii, c = tx + 16 * jj;
            Cb[r * MM + c] = acc[ii][jj];
            Cb[c * MM + r] = acc[ii][jj];
        }
    if (dg) {
#pragma unroll
        for (int ii = 0; ii < 8; ii++) {
            int r = ty + 16 * ii, c = tx + 16 * ii;
            Cb[r * MM + c] = acc[ii][ii];
            Cb[c * MM + r] = acc[ii][ii];
        }
    }
}

// Gauss-Jordan inverse of (C1+C2) -> g_C ----------------------------------
__global__ void __launch_bounds__(256) k_inv() {
    extern __shared__ float sm[];
    float* sM = sm; float* sf = sm + 16384; float* sp = sm + 16512;
    int b = blockIdx.x, t = threadIdx.x;
    float* Cb = g_C + (size_t)b * MM * MM;
    const float* Cb2 = g_C2 + (size_t)b * MM * MM;
    for (int i = t; i < 4096; i += 256) {
        float4 x = ((const float4*)Cb)[i], y = ((const float4*)Cb2)[i];
        ((float4*)sM)[i] = make_float4(x.x + y.x, x.y + y.y, x.z + y.z, x.w + y.w);
    }
    __syncthreads();
    for (int k = 0; k < 128; k++) {
        if (t == 0) sp[0] = 1.0f / sM[k * 128 + k];
        __syncthreads();
        float ipiv = sp[0];
        if (t < 128) {
            float v = sM[k * 128 + t];
            sM[k * 128 + t] = (t == k) ? ipiv : v * ipiv;
            sf[t] = (t == k) ? 0.0f : sM[t * 128 + k];
        }
        __syncthreads();
        int j = t & 127, i0 = (t >> 7) * 64;
        float mk = sM[k * 128 + j];
#pragma unroll 4
        for (int ii = 0; ii < 64; ii++) {
            int i = i0 + ii;
            if (i == k) continue;
            float fi = sf[i];
            float v = sM[i * 128 + j];
            sM[i * 128 + j] = (j == k) ? (-fi * mk) : (v - fi * mk);
        }
        __syncthreads();
    }
    for (int i = t; i < 4096; i += 256) ((float4*)Cb)[i] = ((const float4*)sM)[i];
}

// Iterations: 2-CTA cluster, mbarrier exchange, f32x2 math ----------------
#define OFF_C    0
#define OFF_A    16384
#define OFF_Y    49152
#define OFF_B    49664
#define OFF_R    49792
#define OFF_REM  49920
#define OFF_RT   50176
#define OFF_U    50304
#define OFF_CMB  50432      // 2048 f : pass2 partials [4][512]
#define OFF_MB   52480      // 2 mbarriers
#define SMEM_WORDS 52488

__global__ void __launch_bounds__(512, 1) __cluster_dims__(2, 1, 1)
k_iter(const float* __restrict__ bvec, const float* __restrict__ D1,
       const float* __restrict__ D2, float* __restrict__ out) {
    extern __shared__ float sm[];
    const int t = threadIdx.x, w = t >> 5, l = t & 31;
    const int b = blockIdx.x >> 1;
    const uint32_t rank = blockIdx.x & 1;
    const uint32_t sbase = smem_u32(sm);
    const uint32_t peer = mapa_rank(sbase, rank ^ 1u);

    {   // load C, A-half, b
        float4* d = (float4*)(sm + OFF_C);
        const float4* s = (const float4*)(g_C + (size_t)b * MM * MM);
#pragma unroll
        for (int q = 0; q < 8; q++) d[t + 512 * q] = s[t + 512 * q];
        uint4* da = (uint4*)(sm + OFF_A);
        const uint4* sa = (const uint4*)(g_Ah + (size_t)b * MM * NN + (size_t)rank * 512);
#pragma unroll
        for (int q = 0; q < 16; q++) {
            int i = t + 512 * q, r = i >> 6, c4 = i & 63;
            da[i] = sa[(size_t)r * 128 + c4];
        }
        if (t < 128) sm[OFF_B + t] = bvec[(size_t)b * MM + t];
        if (t == 0) {
            mbar_init(sbase + OFF_MB * 4u, 16);
            mbar_init(sbase + OFF_MB * 4u + 8u, 16);
        }
    }

    float2 thr2 = make_float2(0.f, 0.f), dv2 = make_float2(0.f, 0.f);
    float2 z2 = make_float2(0.f, 0.f), xh2, yv2 = make_float2(0.f, 0.f);
    if (t < 256) {
        float2 d1 = ((const float2*)(D1 + (size_t)b * NN + rank * 512))[t];
        float2 d2 = ((const float2*)(D2 + (size_t)b * NN + rank * 512))[t];
        thr2.x = ALPHA * fabsf(d1.x); thr2.y = ALPHA * fabsf(d1.y);
        dv2.x = 1.0f / (1.0f + 2.0f * ALPHA * d2.x * d2.x);
        dv2.y = 1.0f / (1.0f + 2.0f * ALPHA * d2.y * d2.y);
    }
    __syncthreads();
    cluster_sync_();   // mbar init visible cluster-wide

    for (int it = 0; it < ITERS; it++) {
        const int buf = it & 1;
        // elementwise
        if (t < 256) {
            float a0 = z2.x - thr2.x, c0 = z2.x + thr2.x;
            float a1 = z2.y - thr2.y, c1 = z2.y + thr2.y;
            xh2.x = (a0 > 0.f) ? a0 * dv2.x : ((c0 < 0.f) ? c0 * dv2.x : 0.f);
            xh2.y = (a1 > 0.f) ? a1 * dv2.y : ((c1 < 0.f) ? c1 * dv2.y : 0.f);
            yv2.x = 2.0f * xh2.x - z2.x;
            yv2.y = 2.0f * xh2.y - z2.y;
            ((float2*)(sm + OFF_Y))[t] = yv2;
        }
        __syncthreads();                                  // bar1

        // pass1: warp w rows 8w..8w+7; lane l cols 8*(32h+l)..+7 (contig LDS)
        {
            u64 acc[8];
#pragma unroll
            for (int r = 0; r < 8; r++) acc[r] = 0ull;
            const uint4* a4 = (const uint4*)(sm + OFF_A);
            const u64* yu = (const u64*)(sm + OFF_Y);
#pragma unroll
            for (int h = 0; h < 2; h++) {
                int c = 32 * h + l;
                u64 y0 = yu[4 * c], y1 = yu[4 * c + 1], y2 = yu[4 * c + 2], y3 = yu[4 * c + 3];
#pragma unroll
                for (int rr = 0; rr < 8; rr++) {
                    uint4 p = a4[(8 * w + rr) * 64 + c];
                    fma2(acc[rr], pk(__half22float2(*(__half2*)&p.x)), y0);
                    fma2(acc[rr], pk(__half22float2(*(__half2*)&p.y)), y1);
                    fma2(acc[rr], pk(__half22float2(*(__half2*)&p.z)), y2);
                    fma2(acc[rr], pk(__half22float2(*(__half2*)&p.w)), y3);
                }
            }
            float sacc[8];
#pragma unroll
            for (int r = 0; r < 8; r++) { float2 f = upk(acc[r]); sacc[r] = f.x + f.y; }
#pragma unroll
            for (int off = 16; off > 0; off >>= 1)
#pragma unroll
                for (int r = 0; r < 8; r++)
                    sacc[r] += __shfl_xor_sync(0xffffffffu, sacc[r], off);
            if (l == 0) {
                *(float4*)(sm + OFF_R + 8 * w)     = make_float4(sacc[0], sacc[1], sacc[2], sacc[3]);
                *(float4*)(sm + OFF_R + 8 * w + 4) = make_float4(sacc[4], sacc[5], sacc[6], sacc[7]);
                uint32_t ra = peer + (uint32_t)(OFF_REM + buf * 128 + 8 * w) * 4u;
#pragma unroll
                for (int r = 0; r < 8; r++) st_cluster_f32(ra + 4u * r, sacc[r]);
                mbar_arrive_remote(peer + OFF_MB * 4u + 8u * buf);
            }
        }
        __syncthreads();                                  // bar2: local sr ready

        if (t < 128) {
            mbar_wait_acq(sbase + OFF_MB * 4u + 8u * buf, (uint32_t)((it >> 1) & 1));
            sm[OFF_RT + t] = sm[OFF_R + t] + sm[OFF_REM + buf * 128 + t] - sm[OFF_B + t];
        }
        __syncthreads();                                  // bar3: r_total

        // u = C r (t<256, 2 per row, 4-phase stagger)
        if (t < 256) {
            int i = t >> 1, h = t & 1, base = i & 15;
            float accu = 0.0f;
#pragma unroll
            for (int m = 0; m < 16; m++) {
                int j = 8 * ((base + m) & 15) + 4 * h;
                float4 c4 = *(const float4*)(sm + OFF_C + i * 128 + j);
                float4 r4 = *(const float4*)(sm + OFF_RT + j);
                accu += c4.x * r4.x + c4.y * r4.y + c4.z * r4.z + c4.w * r4.w;
            }
            accu += __shfl_xor_sync(0xffffffffu, accu, 1);
            if (h == 0) sm[OFF_U + i] = accu;
        }
        __syncthreads();                                  // bar4: u ready

        // pass2: thread (g,p): cols 4p..4p+3, rows 32g..32g+31
        {
            int g = t >> 7, p = t & 127;
            u64 c01 = 0ull, c23 = 0ull;
            const uint32_t* au = (const uint32_t*)(sm + OFF_A);
            const float4* u4p = (const float4*)(sm + OFF_U) + g * 8;
#pragma unroll 2
            for (int m = 0; m < 8; m++) {
                float4 u4 = u4p[m];
                int r0 = 32 * g + 4 * m;
#pragma unroll
                for (int rr = 0; rr < 4; rr++) {
                    float uu = (rr == 0) ? u4.x : (rr == 1) ? u4.y : (rr == 2) ? u4.z : u4.w;
                    u64 ub = pk(make_float2(uu, uu));
                    uint2 v = *(const uint2*)(au + (size_t)(r0 + rr) * 256 + 2 * p);
                    fma2(c01, pk(__half22float2(*(__half2*)&v.x)), ub);
                    fma2(c23, pk(__half22float2(*(__half2*)&v.y)), ub);
                }
            }
            float2 f01 = upk(c01), f23 = upk(c23);
            *(float4*)(sm + OFF_CMB + (g * 128 + p) * 4) = make_float4(f01.x, f01.y, f23.x, f23.y);
        }
        __syncthreads();                                  // bar5: partials

        if (t < 256) {
            float cx = 0.f, cy = 0.f;
#pragma unroll
            for (int g = 0; g < 4; g++) {
                float2 pp = *(const float2*)(sm + OFF_CMB + g * 512 + 2 * t);
                cx += pp.x; cy += pp.y;
            }
            z2.x = xh2.x - cx; z2.y = xh2.y - cy;
            yv2.x -= cx; yv2.y -= cy;                     // x_new
        }
    }

    if (t < 256)
        ((float2*)(out + (size_t)b * NN + rank * 512))[t] = yv2;
    cluster_sync_();
}

// --------------------------------------------------------------------------
extern "C" void kernel_launch(void* const* d_in, const int* in_sizes, int n_in,
                              void* d_out, int out_size) {
    const float* A  = (const float*)d_in[0];
    const float* bv = (const float*)d_in[1];
    const float* D1 = (const float*)d_in[2];
    const float* D2 = (const float*)d_in[3];
    float* out = (float*)d_out;

    cudaFuncSetAttribute(k_inv,  cudaFuncAttributeMaxDynamicSharedMemorySize, 66052);
    cudaFuncSetAttribute(k_iter, cudaFuncAttributeMaxDynamicSharedMemorySize, SMEM_WORDS * 4);

    k_convert<<<32768, 256>>>(A);
    k_aat<<<BSZ * 2, 256>>>();
    k_inv<<<BSZ, 256, 66052>>>();
    k_iter<<<BSZ * 2, 512, SMEM_WORDS * 4>>>(bv, D1, D2, out);
}

// round 6
// speedup vs baseline: 1.2989x; 1.0205x over previous
#include <cuda_runtime.h>
#include <cuda_fp16.h>
#include <cstdint>

#define BSZ   256
#define MM    128
#define NN    1024
#define ITERS 100
#define ALPHA 0.1f

__device__ __half g_Ah[(size_t)BSZ * MM * NN];
__device__ float  g_C [(size_t)BSZ * MM * MM];
__device__ float  g_C2[(size_t)BSZ * MM * MM];

__device__ __forceinline__ uint32_t smem_u32(const void* p) {
    uint32_t a;
    asm("{ .reg .u64 t; cvta.to.shared.u64 t, %1; cvt.u32.u64 %0, t; }" : "=r"(a) : "l"(p));
    return a;
}
__device__ __forceinline__ uint32_t mapa_rank(uint32_t addr, uint32_t trank) {
    uint32_t r;
    asm("mapa.shared::cluster.u32 %0, %1, %2;" : "=r"(r) : "r"(addr), "r"(trank));
    return r;
}
__device__ __forceinline__ void cluster_sync_() {
    asm volatile("barrier.cluster.arrive.aligned;" ::: "memory");
    asm volatile("barrier.cluster.wait.aligned;"   ::: "memory");
}
__device__ __forceinline__ void st_cluster_f32(uint32_t addr, float v) {
    asm volatile("st.shared::cluster.f32 [%0], %1;" :: "r"(addr), "f"(v) : "memory");
}
__device__ __forceinline__ void mbar_init(uint32_t a, uint32_t c) {
    asm volatile("mbarrier.init.shared.b64 [%0], %1;" :: "r"(a), "r"(c) : "memory");
}
__device__ __forceinline__ void mbar_arrive_remote(uint32_t ra) {
    asm volatile("mbarrier.arrive.release.cluster.shared::cluster.b64 _, [%0];" :: "r"(ra) : "memory");
}
__device__ __forceinline__ void mbar_wait_acq(uint32_t mb, uint32_t par) {
    asm volatile(
        "{\n\t.reg .pred P;\n\t"
        "WL%=:\n\t"
        "mbarrier.try_wait.parity.acquire.cluster.shared::cta.b64 P, [%0], %1, 0x989680;\n\t"
        "@P bra.uni WD%=;\n\t"
        "bra.uni WL%=;\n\t"
        "WD%=:\n\t}" :: "r"(mb), "r"(par) : "memory");
}
__device__ __forceinline__ void ldsm_x4(uint32_t& a0, uint32_t& a1, uint32_t& a2, uint32_t& a3, uint32_t addr) {
    asm volatile("ldmatrix.sync.aligned.m8n8.x4.shared.b16 {%0,%1,%2,%3}, [%4];"
                 : "=r"(a0), "=r"(a1), "=r"(a2), "=r"(a3) : "r"(addr));
}
__device__ __forceinline__ void ldsm_x4t(uint32_t& a0, uint32_t& a1, uint32_t& a2, uint32_t& a3, uint32_t addr) {
    asm volatile("ldmatrix.sync.aligned.m8n8.x4.trans.shared.b16 {%0,%1,%2,%3}, [%4];"
                 : "=r"(a0), "=r"(a1), "=r"(a2), "=r"(a3) : "r"(addr));
}
__device__ __forceinline__ void mma16816(float& c0, float& c1, float& c2, float& c3,
                                         uint32_t a0, uint32_t a1, uint32_t a2, uint32_t a3,
                                         uint32_t b0, uint32_t b1) {
    asm volatile("mma.sync.aligned.m16n8k16.row.col.f32.f16.f16.f32 "
                 "{%0,%1,%2,%3},{%4,%5,%6,%7},{%8,%9},{%0,%1,%2,%3};"
                 : "+f"(c0), "+f"(c1), "+f"(c2), "+f"(c3)
                 : "r"(a0), "r"(a1), "r"(a2), "r"(a3), "r"(b0), "r"(b1));
}

// --------------------------------------------------------------------------
__global__ void k_convert(const float* __restrict__ A) {
    size_t i = ((size_t)blockIdx.x * blockDim.x + threadIdx.x) * 4;
    float4 v = *(const float4*)(A + i);
    __half2* dst = (__half2*)(g_Ah + i);
    dst[0] = __floats2half2_rn(v.x, v.y);
    dst[1] = __floats2half2_rn(v.z, v.w);
}

// AAT partials (triangle + K-split 2) -------------------------------------
__global__ void __launch_bounds__(256) k_aat() {
    __shared__ float sA[128 * 33];
    int b = blockIdx.x >> 1, kc = blockIdx.x & 1, t = threadIdx.x;
    const __half* Ab = g_Ah + (size_t)b * MM * NN;
    int ty = t >> 4, tx = t & 15;
    bool dg = (ty >= tx);
    float acc[8][8];
#pragma unroll
    for (int ii = 0; ii < 8; ii++)
#pragma unroll
        for (int jj = 0; jj < 8; jj++) acc[ii][jj] = 0.0f;

    for (int ks = 0; ks < 16; ks++) {
        int k0 = kc * 512 + ks * 32;
        int tr = t >> 1, tc0 = (t & 1) * 16;
        const __half2* src = (const __half2*)(Ab + (size_t)tr * NN + k0 + tc0);
        float* dst = &sA[tr * 33 + tc0];
#pragma unroll
        for (int q = 0; q < 8; q++) {
            float2 f = __half22float2(src[q]);
            dst[2 * q] = f.x; dst[2 * q + 1] = f.y;
        }
        __syncthreads();
#pragma unroll 2
        for (int kk = 0; kk < 32; kk++) {
            float a[8], c[8];
#pragma unroll
            for (int ii = 0; ii < 8; ii++) a[ii] = sA[(ty + 16 * ii) * 33 + kk];
#pragma unroll
            for (int jj = 0; jj < 8; jj++) c[jj] = sA[(tx + 16 * jj) * 33 + kk];
#pragma unroll
            for (int ii = 1; ii < 8; ii++)
#pragma unroll
                for (int jj = 0; jj < ii; jj++) acc[ii][jj] += a[ii] * c[jj];
            if (dg) {
#pragma unroll
                for (int ii = 0; ii < 8; ii++) acc[ii][ii] += a[ii] * c[ii];
            }
        }
        __syncthreads();
    }
    float* Cb = (kc ? g_C2 : g_C) + (size_t)b * MM * MM;
#pragma unroll
    for (int ii = 1; ii < 8; ii++)
#pragma unroll
        for (int jj = 0; jj < ii; jj++) {
            int r = ty + 16 * ii, c = tx + 16 * jj;
            Cb[r * MM + c] = acc[ii][jj];
            Cb[c * MM + r] = acc[ii][jj];
        }
    if (dg) {
#pragma unroll
        for (int ii = 0; ii < 8; ii++) {
            int r = ty + 16 * ii, c = tx + 16 * ii;
            Cb[r * MM + c] = acc[ii][ii];
            Cb[c * MM + r] = acc[ii][ii];
        }
    }
}

// Gauss-Jordan inverse of (C1+C2) -> g_C ----------------------------------
__global__ void __launch_bounds__(256) k_inv() {
    extern __shared__ float sm[];
    float* sM = sm; float* sf = sm + 16384; float* sp = sm + 16512;
    int b = blockIdx.x, t = threadIdx.x;
    float* Cb = g_C + (size_t)b * MM * MM;
    const float* Cb2 = g_C2 + (size_t)b * MM * MM;
    for (int i = t; i < 4096; i += 256) {
        float4 x = ((const float4*)Cb)[i], y = ((const float4*)Cb2)[i];
        ((float4*)sM)[i] = make_float4(x.x + y.x, x.y + y.y, x.z + y.z, x.w + y.w);
    }
    __syncthreads();
    for (int k = 0; k < 128; k++) {
        if (t == 0) sp[0] = 1.0f / sM[k * 128 + k];
        __syncthreads();
        float ipiv = sp[0];
        if (t < 128) {
            float v = sM[k * 128 + t];
            sM[k * 128 + t] = (t == k) ? ipiv : v * ipiv;
            sf[t] = (t == k) ? 0.0f : sM[t * 128 + k];
        }
        __syncthreads();
        int j = t & 127, i0 = (t >> 7) * 64;
        float mk = sM[k * 128 + j];
#pragma unroll 4
        for (int ii = 0; ii < 64; ii++) {
            int i = i0 + ii;
            if (i == k) continue;
            float fi = sf[i];
            float v = sM[i * 128 + j];
            sM[i * 128 + j] = (j == k) ? (-fi * mk) : (v - fi * mk);
        }
        __syncthreads();
    }
    for (int i = t; i < 4096; i += 256) ((float4*)Cb)[i] = ((const float4*)sM)[i];
}

// Iterations: 2-CTA cluster, HMMA GEMVs, split-fp16 vectors ----------------
// A in smem padded: 128 rows x 1040 bytes (65 uint4/row) -> conflict-free ldmatrix
#define APAD_U4  65
#define OFF_C    0                     // 16384 f
#define OFF_A    16384                 // 33280 w (128*260 u32)
#define OFF_YH   49664                 // 256 u32 (half2 y_hi)
#define OFF_YL   49920                 // 256 u32
#define OFF_B    50176                 // 128 f
#define OFF_SR0  50304                 // 128 f (khalf 0 partial)
#define OFF_SR1  50432                 // 128 f (khalf 1 partial)
#define OFF_REM  50560                 // 256 f (peer partial, 2 bufs)
#define OFF_RT   50816                 // 128 f
#define OFF_UH   50944                 // 64 u32 (half2 u_hi)
#define OFF_UL   51008                 // 64 u32
#define OFF_CORR 51072                 // 512 f
#define OFF_MB   51584                 // 2 x u64 mbarriers
#define SMEM_WORDS 51588               // 206352 bytes

__global__ void __launch_bounds__(512, 1) __cluster_dims__(2, 1, 1)
k_iter(const float* __restrict__ bvec, const float* __restrict__ D1,
       const float* __restrict__ D2, float* __restrict__ out) {
    extern __shared__ float sm[];
    const int t = threadIdx.x, w = t >> 5, l = t & 31;
    const int b = blockIdx.x >> 1;
    const uint32_t rank = blockIdx.x & 1;
    const uint32_t sbase = smem_u32(sm);
    const uint32_t peer = mapa_rank(sbase, rank ^ 1u);
    const uint32_t aA = sbase + OFF_A * 4u;

    {   // load C, padded A-half, b
        float4* d = (float4*)(sm + OFF_C);
        const float4* s = (const float4*)(g_C + (size_t)b * MM * MM);
#pragma unroll
        for (int q = 0; q < 8; q++) d[t + 512 * q] = s[t + 512 * q];
        uint4* da = (uint4*)(sm + OFF_A);
        const uint4* sa = (const uint4*)(g_Ah + (size_t)b * MM * NN + (size_t)rank * 512);
#pragma unroll
        for (int q = 0; q < 16; q++) {
            int i = t + 512 * q, r = i >> 6, c4 = i & 63;
            da[r * APAD_U4 + c4] = sa[(size_t)r * 128 + c4];
        }
        if (t < 128) sm[OFF_B + t] = bvec[(size_t)b * MM + t];
        if (t == 0) {
            mbar_init(sbase + OFF_MB * 4u, 128);
            mbar_init(sbase + OFF_MB * 4u + 8u, 128);
        }
    }

    // per-thread state: t<256 owns local cols 2t, 2t+1
    float2 thr2 = make_float2(0.f, 0.f), dv2 = make_float2(0.f, 0.f);
    float2 z2 = make_float2(0.f, 0.f), xh2, yv2 = make_float2(0.f, 0.f);
    if (t < 256) {
        float2 d1 = ((const float2*)(D1 + (size_t)b * NN + rank * 512))[t];
        float2 d2 = ((const float2*)(D2 + (size_t)b * NN + rank * 512))[t];
        thr2.x = ALPHA * fabsf(d1.x); thr2.y = ALPHA * fabsf(d1.y);
        dv2.x = 1.0f / (1.0f + 2.0f * ALPHA * d2.x * d2.x);
        dv2.y = 1.0f / (1.0f + 2.0f * ALPHA * d2.y * d2.y);
    }
    __syncthreads();
    cluster_sync_();

    // pass1 per-warp constants: warp w -> m-tile rows 16*(w&7), k-half w>>3
    const int p1_m0 = (w & 7) * 16, p1_kh = w >> 3;
    const uint32_t p1_addr = aA + (uint32_t)(p1_m0 + (l & 15)) * 1040u
                           + (uint32_t)(p1_kh * 512) + (uint32_t)((l >> 4) << 4);
    const int bc = l & 3;              // tid%4: b-frag k-subgroup
    // pass2: warp w -> m-tiles (cols) 2w, 2w+1
    const uint32_t p2_rowoff = (uint32_t)((l & 7) + ((l >> 4) << 3)) * 1040u
                             + (uint32_t)((l & 8) << 1);

    for (int it = 0; it < ITERS; it++) {
        const int buf = it & 1;
        // --- elementwise: soft-threshold, y = 2x_half - z, split to fp16 hi/lo
        if (t < 256) {
            float a0 = z2.x - thr2.x, c0 = z2.x + thr2.x;
            float a1 = z2.y - thr2.y, c1 = z2.y + thr2.y;
            xh2.x = (a0 > 0.f) ? a0 * dv2.x : ((c0 < 0.f) ? c0 * dv2.x : 0.f);
            xh2.y = (a1 > 0.f) ? a1 * dv2.y : ((c1 < 0.f) ? c1 * dv2.y : 0.f);
            yv2.x = 2.0f * xh2.x - z2.x;
            yv2.y = 2.0f * xh2.y - z2.y;
            __half2 hy = __floats2half2_rn(yv2.x, yv2.y);
            float2 fy = __half22float2(hy);
            __half2 ly = __floats2half2_rn(yv2.x - fy.x, yv2.y - fy.y);
            ((uint32_t*)(sm + OFF_YH))[t] = *(uint32_t*)&hy;
            ((uint32_t*)(sm + OFF_YL))[t] = *(uint32_t*)&ly;
        }
        __syncthreads();                                   // bar1: y ready

        // --- pass 1 (HMMA): r_partial[kh] = A[:, kh*256..] * y[kh half] ---
        {
            float c0 = 0.f, c1 = 0.f, c2 = 0.f, c3 = 0.f;
            const uint32_t* yh = (const uint32_t*)(sm + OFF_YH) + p1_kh * 128;
            const uint32_t* yl = (const uint32_t*)(sm + OFF_YL) + p1_kh * 128;
            uint32_t addr = p1_addr;
#pragma unroll
            for (int kt = 0; kt < 16; kt++) {
                uint32_t a0, a1, a2, a3;
                ldsm_x4(a0, a1, a2, a3, addr);
                addr += 32u;                                // +16 halves
                int kb = kt * 8 + bc;
                mma16816(c0, c1, c2, c3, a0, a1, a2, a3, yh[kb], yh[kb + 4]);
                mma16816(c0, c1, c2, c3, a0, a1, a2, a3, yl[kb], yl[kb + 4]);
            }
            if ((l & 3) == 0) {
                float* srp = sm + (p1_kh ? OFF_SR1 : OFF_SR0);
                srp[p1_m0 + (l >> 2)]     = c0;
                srp[p1_m0 + 8 + (l >> 2)] = c2;
            }
        }
        __syncthreads();                                   // bar2: partials ready

        // --- exchange + r_total (t<128) ---
        if (t < 128) {
            float s = sm[OFF_SR0 + t] + sm[OFF_SR1 + t];
            st_cluster_f32(peer + (uint32_t)(OFF_REM + buf * 128 + t) * 4u, s);
            mbar_arrive_remote(peer + OFF_MB * 4u + 8u * buf);
            mbar_wait_acq(sbase + OFF_MB * 4u + 8u * buf, (uint32_t)((it >> 1) & 1));
            sm[OFF_RT + t] = s + sm[OFF_REM + buf * 128 + t] - sm[OFF_B + t];
        }
        __syncthreads();                                   // bar3: rt ready

        // --- u = C * rt (t<256, 2/row), then split u to fp16 hi/lo ---
        if (t < 256) {
            int i = t >> 1, h = t & 1, base = i & 15;
            float accu = 0.0f;
#pragma unroll
            for (int m = 0; m < 16; m++) {
                int j = 8 * ((base + m) & 15) + 4 * h;
                float4 c4 = *(const float4*)(sm + OFF_C + i * 128 + j);
                float4 r4 = *(const float4*)(sm + OFF_RT + j);
                accu += c4.x * r4.x + c4.y * r4.y + c4.z * r4.z + c4.w * r4.w;
            }
            accu += __shfl_xor_sync(0xffffffffu, accu, 1); // both lanes hold u_i
            float un = __shfl_down_sync(0xffffffffu, accu, 2);   // u_{i+1}
            if ((t & 3) == 0) {
                __half2 hu = __floats2half2_rn(accu, un);
                float2 fu = __half22float2(hu);
                __half2 lu = __floats2half2_rn(accu - fu.x, un - fu.y);
                ((uint32_t*)(sm + OFF_UH))[t >> 2] = *(uint32_t*)&hu;
                ((uint32_t*)(sm + OFF_UL))[t >> 2] = *(uint32_t*)&lu;
            }
        }
        __syncthreads();                                   // bar4: u ready

        // --- pass 2 (HMMA, ldmatrix.trans): corr = A^T * u ---
        {
            const uint32_t* uh = (const uint32_t*)(sm + OFF_UH);
            const uint32_t* ul = (const uint32_t*)(sm + OFF_UL);
#pragma unroll
            for (int mi = 0; mi < 2; mi++) {
                int mt = 2 * w + mi, cc0 = mt * 16;
                float d0 = 0.f, d1 = 0.f, d2 = 0.f, d3 = 0.f;
                uint32_t addr = aA + p2_rowoff + (uint32_t)(cc0 * 2);
#pragma unroll
                for (int kt = 0; kt < 8; kt++) {
                    uint32_t a0, a1, a2, a3;
                    ldsm_x4t(a0, a1, a2, a3, addr);
                    addr += 16u * 1040u;                    // +16 rows
                    int kb = kt * 8 + bc;
                    mma16816(d0, d1, d2, d3, a0, a1, a2, a3, uh[kb], uh[kb + 4]);
                    mma16816(d0, d1, d2, d3, a0, a1, a2, a3, ul[kb], ul[kb + 4]);
                }
                if ((l & 3) == 0) {
                    sm[OFF_CORR + cc0 + (l >> 2)]     = d0;
                    sm[OFF_CORR + cc0 + 8 + (l >> 2)] = d2;
                }
            }
        }
        __syncthreads();                                   // bar5: corr ready

        // --- epilogue: z' = x_half - corr, x_new = y - corr ---
        if (t < 256) {
            float2 cr = *(const float2*)(sm + OFF_CORR + 2 * t);
            z2.x = xh2.x - cr.x; z2.y = xh2.y - cr.y;
            yv2.x -= cr.x; yv2.y -= cr.y;                  // x_new
        }
    }

    if (t < 256)
        ((float2*)(out + (size_t)b * NN + rank * 512))[t] = yv2;
    cluster_sync_();
}

// --------------------------------------------------------------------------
extern "C" void kernel_launch(void* const* d_in, const int* in_sizes, int n_in,
                              void* d_out, int out_size) {
    const float* A  = (const float*)d_in[0];
    const float* bv = (const float*)d_in[1];
    const float* D1 = (const float*)d_in[2];
    const float* D2 = (const float*)d_in[3];
    float* out = (float*)d_out;

    cudaFuncSetAttribute(k_inv,  cudaFuncAttributeMaxDynamicSharedMemorySize, 66052);
    cudaFuncSetAttribute(k_iter, cudaFuncAttributeMaxDynamicSharedMemorySize, SMEM_WORDS * 4);

    k_convert<<<32768, 256>>>(A);
    k_aat<<<BSZ * 2, 256>>>();
    k_inv<<<BSZ, 256, 66052>>>();
    k_iter<<<BSZ * 2, 512, SMEM_WORDS * 4>>>(bv, D1, D2, out);
}